// round 16
// baseline (speedup 1.0000x reference)
#include <cuda_runtime.h>
#include <cuda_bf16.h>
#include <math.h>
#include <stdint.h>

#define NB 8
#define LSEQ 2048
#define CDIM 512
#define HDIM 512
#define CHALF 256
typedef __nv_bfloat16 bf16;

// ---------------- scratch (device globals: allocation-guard safe) ----------
__device__ __align__(1024) bf16 g_xb  [(size_t)NB * LSEQ * CDIM];
__device__ __align__(1024) bf16 g_wth [CDIM * HDIM];     // [K,N] bf16 copies
__device__ __align__(1024) bf16 g_wph [CDIM * HDIM];
__device__ __align__(1024) bf16 g_wps [CDIM * HDIM];
__device__ __align__(1024) bf16 g_wr1 [HDIM * CHALF];
__device__ __align__(1024) bf16 g_wr2 [CHALF * CDIM];
__device__ __align__(1024) bf16 g_xt  [(size_t)NB * LSEQ * HDIM];
__device__ __align__(1024) bf16 g_xph [(size_t)NB * LSEQ * HDIM];
__device__ __align__(1024) bf16 g_xpsi[(size_t)NB * LSEQ * HDIM];
__device__ __align__(1024) bf16 g_P   [(size_t)NB * LSEQ * LSEQ];  // bf16 exp(logits)
__device__ __align__(1024) float g_rs [(size_t)NB * LSEQ];         // 1/rowsum
__device__ __align__(1024) bf16 g_xadd[(size_t)NB * LSEQ * HDIM];
__device__ __align__(1024) bf16 g_h1  [(size_t)NB * LSEQ * CHALF];

// smem: A stages 0/10240 (128 rows x 80B); B stages 20480/30720
//   non-TRB B: 128 rows x 80B pitch ([N,K] tile)
//   TRB B:      32 rows x 272B pitch ([K,N] tile)  (8704B <= 10240)
#define GEMM_SMEM 40960

// ---------------- asm helpers ------------------------------------------------
__device__ __forceinline__ void cp16(uint32_t dst, const void* src) {
    asm volatile("cp.async.cg.shared.global [%0], [%1], 16;"
                 :: "r"(dst), "l"(src) : "memory");
}
#define CP_COMMIT() asm volatile("cp.async.commit_group;" ::: "memory")
#define CP_WAIT1()  asm volatile("cp.async.wait_group 1;" ::: "memory")
#define CP_WAIT0()  asm volatile("cp.async.wait_group 0;" ::: "memory")

__device__ __forceinline__ void ldsm4(uint32_t* r, uint32_t addr) {
    asm volatile("ldmatrix.sync.aligned.m8n8.x4.shared.b16 {%0,%1,%2,%3}, [%4];"
                 : "=r"(r[0]), "=r"(r[1]), "=r"(r[2]), "=r"(r[3]) : "r"(addr));
}
__device__ __forceinline__ void ldsm4t(uint32_t* r, uint32_t addr) {
    asm volatile("ldmatrix.sync.aligned.m8n8.x4.trans.shared.b16 {%0,%1,%2,%3}, [%4];"
                 : "=r"(r[0]), "=r"(r[1]), "=r"(r[2]), "=r"(r[3]) : "r"(addr));
}
__device__ __forceinline__ void mma_bf16(float* c, const uint32_t* a, const uint32_t* b) {
    asm volatile("mma.sync.aligned.m16n8k16.row.col.f32.bf16.bf16.f32 "
                 "{%0,%1,%2,%3},{%4,%5,%6,%7},{%8,%9},{%0,%1,%2,%3};"
                 : "+f"(c[0]), "+f"(c[1]), "+f"(c[2]), "+f"(c[3])
                 : "r"(a[0]), "r"(a[1]), "r"(a[2]), "r"(a[3]), "r"(b[0]), "r"(b[1]));
}

// ---------------- universal bf16 tensor-core GEMM ----------------------------
// TRB=0: C = A[M,K] @ Bt[N,K]^T  (B row stride K, non-trans ldmatrix)
// TRB=1: C = A[M,K] @ B[K,N]     (B row stride N, trans ldmatrix)
// Tile 128x128, BK=32, 2-stage cp.async. Mainloop identical to R9 champion.
// EPI: 0 bias->bf16 | 4 bias+leaky->bf16 | 5 bias+tanh+res->fp32
//      7 exp->bf16 (logits)      | 8 scale-by-res[row] ->bf16 (AV normalize)
template <int EPI, bool TRB>
__global__ void __launch_bounds__(256)
gemm5(const bf16* __restrict__ A, const bf16* __restrict__ B,
      const float* __restrict__ bias, const float* __restrict__ res,
      void* __restrict__ Cout, int M, int N, int K, long sA, long sB, long sC)
{
    extern __shared__ __align__(1024) char smem[];
    uint32_t sbase = (uint32_t)__cvta_generic_to_shared(smem);
    const int tid = threadIdx.x, wid = tid >> 5, lane = tid & 31;

    A += (long)blockIdx.z * sA;
    B += (long)blockIdx.z * sB;
    const int m0 = blockIdx.y * 128, n0 = blockIdx.x * 128;

    const int wm = wid >> 2, wn = wid & 3;        // 2x4 warp grid
    const int m_off = wm * 64, n_off = wn * 32;

    float acc[4][4][4];
#pragma unroll
    for (int i = 0; i < 4; i++)
#pragma unroll
        for (int j = 0; j < 4; j++)
#pragma unroll
            for (int u = 0; u < 4; u++) acc[i][j][u] = 0.f;

    const int KT = K >> 5;
    auto ldA = [&](int kt, int buf) {
#pragma unroll
        for (int s = 0; s < 2; s++) {
            int ch = s * 256 + tid;
            int r = ch >> 2, seg = ch & 3;
            cp16(sbase + buf * 10240u + r * 80u + seg * 16u,
                 A + (long)(m0 + r) * K + kt * 32 + seg * 8);
        }
    };
    auto ldB = [&](int kt, int buf) {
        if (!TRB) {
#pragma unroll
            for (int s = 0; s < 2; s++) {
                int ch = s * 256 + tid;
                int r = ch >> 2, seg = ch & 3;
                cp16(sbase + 20480u + buf * 10240u + r * 80u + seg * 16u,
                     B + (long)(n0 + r) * K + kt * 32 + seg * 8);
            }
        } else {
            // [K,N] tile: 32 rows x 256B, pitch 272B
#pragma unroll
            for (int s = 0; s < 2; s++) {
                int ch = s * 256 + tid;
                int r = ch >> 4, seg = ch & 15;
                cp16(sbase + 20480u + buf * 10240u + r * 272u + seg * 16u,
                     B + (long)(kt * 32 + r) * N + n0 + seg * 8);
            }
        }
    };

    ldA(0, 0); ldB(0, 0); CP_COMMIT();

    // ldmatrix lane addressing (constant across k-steps)
    const int a_row = m_off + (lane & 15);
    const int a_kof = (lane >> 4) * 8;
    const int b_row = n_off + (lane & 7) + ((lane >> 4) & 1) * 8;
    const int b_kof = ((lane >> 3) & 1) * 8;
    const int t_krow = ((lane >> 3) & 1) * 8 + (lane & 7);
    const int t_ncol = n_off + ((lane >> 4) & 1) * 8;

    for (int kt = 0; kt < KT; kt++) {
        const int buf = kt & 1;
        if (kt + 1 < KT) {
            ldA(kt + 1, buf ^ 1); ldB(kt + 1, buf ^ 1);
            CP_COMMIT(); CP_WAIT1();
        } else {
            CP_WAIT0();
        }
        __syncthreads();
        const uint32_t Ab = sbase + buf * 10240u;
        const uint32_t Bb = sbase + 20480u + buf * 10240u;
#pragma unroll
        for (int kk = 0; kk < 32; kk += 16) {
            uint32_t a[4][4], bq[2][4];
#pragma unroll
            for (int mt = 0; mt < 4; mt++)
                ldsm4(a[mt], Ab + ((a_row + mt * 16) * 40 + kk + a_kof) * 2);
            if (!TRB) {
#pragma unroll
                for (int p = 0; p < 2; p++)
                    ldsm4(bq[p], Bb + ((b_row + p * 16) * 40 + kk + b_kof) * 2);
            } else {
#pragma unroll
                for (int p = 0; p < 2; p++)
                    ldsm4t(bq[p], Bb + ((kk + t_krow) * 136 + t_ncol + p * 16) * 2);
            }
#pragma unroll
            for (int mt = 0; mt < 4; mt++)
#pragma unroll
                for (int nt = 0; nt < 4; nt++)
                    mma_bf16(acc[mt][nt], a[mt], &bq[nt >> 1][(nt & 1) * 2]);
        }
        __syncthreads();
    }

    // ---- epilogue ----
    const int l4 = lane >> 2, l2 = (lane & 3) * 2;
#pragma unroll
    for (int mt = 0; mt < 4; mt++) {
#pragma unroll
        for (int nt = 0; nt < 4; nt++) {
            int row = m0 + m_off + mt * 16 + l4;
            int col = n0 + n_off + nt * 8 + l2;
            float c0 = acc[mt][nt][0], c1 = acc[mt][nt][1];
            float c2 = acc[mt][nt][2], c3 = acc[mt][nt][3];
            if (EPI == 0 || EPI == 4 || EPI == 5) {
                float b0 = bias[col], b1 = bias[col + 1];
                c0 += b0; c1 += b1; c2 += b0; c3 += b1;
            }
            if (EPI == 4) {
                c0 = fmaxf(c0, 0.2f * c0); c1 = fmaxf(c1, 0.2f * c1);
                c2 = fmaxf(c2, 0.2f * c2); c3 = fmaxf(c3, 0.2f * c3);
            }
            if (EPI == 5) {
                const float2 r0 = *(const float2*)(res + (long)row * N + col);
                const float2 r1 = *(const float2*)(res + (long)(row + 8) * N + col);
                c0 = tanhf(c0) + r0.x; c1 = tanhf(c1) + r0.y;
                c2 = tanhf(c2) + r1.x; c3 = tanhf(c3) + r1.y;
            }
            if (EPI == 7) {                       // unnormalized softmax numerator
                c0 = __expf(c0); c1 = __expf(c1);
                c2 = __expf(c2); c3 = __expf(c3);
            }
            if (EPI == 8) {                       // normalize by 1/rowsum
                const float* inv = res + (long)blockIdx.z * LSEQ;
                float i0 = inv[row - m0 + m0];    // inv indexed by local batch row
                float i1 = inv[row + 8 - m0 + m0];
                // rows here are block-local within the batch (M = LSEQ for AV)
                i0 = inv[row]; i1 = inv[row + 8];
                c0 *= i0; c1 *= i0; c2 *= i1; c3 *= i1;
            }
            if (EPI == 5) {
                float* Cf = (float*)Cout + (long)blockIdx.z * sC;
                *(float2*)(Cf + (long)row * N + col)       = make_float2(c0, c1);
                *(float2*)(Cf + (long)(row + 8) * N + col) = make_float2(c2, c3);
            } else {
                bf16* Cb = (bf16*)Cout + (long)blockIdx.z * sC;
                *(__nv_bfloat162*)(Cb + (long)row * N + col)       = __floats2bfloat162_rn(c0, c1);
                *(__nv_bfloat162*)(Cb + (long)(row + 8) * N + col) = __floats2bfloat162_rn(c2, c3);
            }
        }
    }
}

// ---------------- row sum of bf16 P' -> 1/sum (deterministic) ----------------
__global__ void __launch_bounds__(256)
rowsum_k(const bf16* __restrict__ P, float* __restrict__ inv)
{
    long base = (long)blockIdx.x * LSEQ;
    const uint4* P8 = (const uint4*)(P + base);     // 8 bf16 per uint4
    int tid = threadIdx.x;
    __shared__ float red[256];

    uint4 v = P8[tid];                               // 256 x 8 = 2048
    const __nv_bfloat162* h = (const __nv_bfloat162*)&v;
    float s = 0.f;
#pragma unroll
    for (int i = 0; i < 4; i++) {
        float2 f = __bfloat1622float2(h[i]);
        s += f.x + f.y;
    }
    red[tid] = s;
    __syncthreads();
    for (int st = 128; st > 0; st >>= 1) {
        if (tid < st) red[tid] += red[tid + st];
        __syncthreads();
    }
    if (tid == 0) inv[blockIdx.x] = 1.f / red[0];
}

// ---------------- conversions ------------------------------------------------
__global__ void __launch_bounds__(256)
f2b_k(const float* __restrict__ in, bf16* __restrict__ out, int n4)
{
    int i = blockIdx.x * 256 + threadIdx.x;
    if (i < n4) {
        float4 v = ((const float4*)in)[i];
        ((__nv_bfloat162*)out)[2 * i]     = __floats2bfloat162_rn(v.x, v.y);
        ((__nv_bfloat162*)out)[2 * i + 1] = __floats2bfloat162_rn(v.z, v.w);
    }
}

// all 5 weights fp32 -> bf16 (same [K,N] layout, no transpose) in one launch
__global__ void __launch_bounds__(256)
w2b_k(const float* __restrict__ thw, const float* __restrict__ phw,
      const float* __restrict__ psw, const float* __restrict__ r1w,
      const float* __restrict__ r2w,
      bf16* __restrict__ oth, bf16* __restrict__ oph, bf16* __restrict__ ops,
      bf16* __restrict__ or1, bf16* __restrict__ or2)
{
    int i = blockIdx.x * 256 + threadIdx.x;      // float4 index, 262144 total
    const float* src;
    bf16* dst;
    int off;
    if (i < 196608) {
        int w = i / 65536; off = i - w * 65536;
        src = (w == 0) ? thw : (w == 1) ? phw : psw;
        dst = (w == 0) ? oth : (w == 1) ? oph : ops;
    } else if (i < 229376) {
        off = i - 196608; src = r1w; dst = or1;
    } else {
        off = i - 229376; src = r2w; dst = or2;
    }
    float4 v = ((const float4*)src)[off];
    ((__nv_bfloat162*)dst)[2 * off]     = __floats2bfloat162_rn(v.x, v.y);
    ((__nv_bfloat162*)dst)[2 * off + 1] = __floats2bfloat162_rn(v.z, v.w);
}

// ---------------- launch ----------------------------------------------------
extern "C" void kernel_launch(void* const* d_in, const int* in_sizes, int n_in,
                              void* d_out, int out_size)
{
    const float* x   = (const float*)d_in[0];
    const float* thw = (const float*)d_in[1];
    const float* thb = (const float*)d_in[2];
    const float* phw = (const float*)d_in[3];
    const float* phb = (const float*)d_in[4];
    const float* psw = (const float*)d_in[5];
    const float* psb = (const float*)d_in[6];
    const float* r1w = (const float*)d_in[7];
    const float* r1b = (const float*)d_in[8];
    const float* r2w = (const float*)d_in[9];
    const float* r2b = (const float*)d_in[10];
    float* out = (float*)d_out;

    bf16 *p_xb, *p_wth, *p_wph, *p_wps, *p_wr1, *p_wr2;
    bf16 *p_xt, *p_xph, *p_xpsi, *p_P, *p_xadd, *p_h1;
    float *p_rs;
    cudaGetSymbolAddress((void**)&p_xb,   g_xb);
    cudaGetSymbolAddress((void**)&p_wth,  g_wth);
    cudaGetSymbolAddress((void**)&p_wph,  g_wph);
    cudaGetSymbolAddress((void**)&p_wps,  g_wps);
    cudaGetSymbolAddress((void**)&p_wr1,  g_wr1);
    cudaGetSymbolAddress((void**)&p_wr2,  g_wr2);
    cudaGetSymbolAddress((void**)&p_xt,   g_xt);
    cudaGetSymbolAddress((void**)&p_xph,  g_xph);
    cudaGetSymbolAddress((void**)&p_xpsi, g_xpsi);
    cudaGetSymbolAddress((void**)&p_P,    g_P);
    cudaGetSymbolAddress((void**)&p_rs,   g_rs);
    cudaGetSymbolAddress((void**)&p_xadd, g_xadd);
    cudaGetSymbolAddress((void**)&p_h1,   g_h1);

    cudaFuncSetAttribute((const void*)gemm5<0, true>,  cudaFuncAttributeMaxDynamicSharedMemorySize, GEMM_SMEM);
    cudaFuncSetAttribute((const void*)gemm5<7, false>, cudaFuncAttributeMaxDynamicSharedMemorySize, GEMM_SMEM);
    cudaFuncSetAttribute((const void*)gemm5<8, true>,  cudaFuncAttributeMaxDynamicSharedMemorySize, GEMM_SMEM);
    cudaFuncSetAttribute((const void*)gemm5<4, true>,  cudaFuncAttributeMaxDynamicSharedMemorySize, GEMM_SMEM);
    cudaFuncSetAttribute((const void*)gemm5<5, true>,  cudaFuncAttributeMaxDynamicSharedMemorySize, GEMM_SMEM);

    const int M = NB * LSEQ;                 // 16384
    const long sLH = (long)LSEQ * HDIM;
    const long sLL = (long)LSEQ * LSEQ;
    dim3 gproj(HDIM / 128, M / 128, 1);

    // launches ordered so #6 (ncu -s 5 -c 1) is the logits GEMM
    f2b_k<<<(M * CDIM / 4 + 255) / 256, 256>>>(x, p_xb, M * CDIM / 4);          // 1
    w2b_k<<<1024, 256>>>(thw, phw, psw, r1w, r2w,                               // 2
                         p_wth, p_wph, p_wps, p_wr1, p_wr2);
    gemm5<0, true><<<gproj, 256, GEMM_SMEM>>>(p_xb, p_wth, thb, nullptr, p_xt,  // 3
                                              M, HDIM, CDIM, 0, 0, 0);
    gemm5<0, true><<<gproj, 256, GEMM_SMEM>>>(p_xb, p_wph, phb, nullptr, p_xph, // 4
                                              M, HDIM, CDIM, 0, 0, 0);
    gemm5<0, true><<<gproj, 256, GEMM_SMEM>>>(p_xb, p_wps, psb, nullptr, p_xpsi,// 5
                                              M, HDIM, CDIM, 0, 0, 0);
    // 6: logits -> P' = exp(s) in bf16 (no fp32 S, no separate softmax)
    gemm5<7, false><<<dim3(LSEQ / 128, LSEQ / 128, NB), 256, GEMM_SMEM>>>(
        p_xph, p_xt, nullptr, nullptr, p_P, LSEQ, LSEQ, HDIM, sLH, sLH, sLL);
    // 7: deterministic row sums -> 1/sum
    rowsum_k<<<NB * LSEQ, 256>>>(p_P, p_rs);
    // 8: x_add = (P' @ x_psi) * inv[row]
    gemm5<8, true><<<dim3(HDIM / 128, LSEQ / 128, NB), 256, GEMM_SMEM>>>(
        p_P, p_xpsi, nullptr, p_rs, p_xadd, LSEQ, HDIM, LSEQ, sLL, sLH, sLH);
    // 9: h1 = leaky_relu(x_add @ r1w + r1b)
    gemm5<4, true><<<dim3(CHALF / 128, M / 128, 1), 256, GEMM_SMEM>>>(
        p_xadd, p_wr1, r1b, nullptr, p_h1, M, CHALF, HDIM, 0, 0, 0);
    // 10: out = x + tanh(h1 @ r2w + r2b)
    gemm5<5, true><<<dim3(CDIM / 128, M / 128, 1), 256, GEMM_SMEM>>>(
        p_h1, p_wr2, r2b, x, out, M, CDIM, CHALF, 0, 0, 0);
}

// round 17
// speedup vs baseline: 1.5579x; 1.5579x over previous
#include <cuda_runtime.h>
#include <cuda_bf16.h>
#include <math.h>
#include <stdint.h>

#define NB 8
#define LSEQ 2048
#define CDIM 512
#define HDIM 512
#define CHALF 256
typedef __nv_bfloat16 bf16;

// ---------------- scratch (device globals: allocation-guard safe) ----------
__device__ __align__(1024) bf16 g_xb  [(size_t)NB * LSEQ * CDIM];
__device__ __align__(1024) bf16 g_wth [CDIM * HDIM];     // [K,N] bf16 copies
__device__ __align__(1024) bf16 g_wph [CDIM * HDIM];
__device__ __align__(1024) bf16 g_wps [CDIM * HDIM];
__device__ __align__(1024) bf16 g_wr1 [HDIM * CHALF];
__device__ __align__(1024) bf16 g_wr2 [CHALF * CDIM];
__device__ __align__(1024) bf16 g_xt  [(size_t)NB * LSEQ * HDIM];
__device__ __align__(1024) bf16 g_xph [(size_t)NB * LSEQ * HDIM];
__device__ __align__(1024) bf16 g_xpsi[(size_t)NB * LSEQ * HDIM];
__device__ __align__(1024) bf16 g_P   [(size_t)NB * LSEQ * LSEQ];  // bf16 exp(logits)
__device__ __align__(1024) float g_rs [(size_t)NB * LSEQ];         // 1/rowsum
__device__ __align__(1024) bf16 g_xadd[(size_t)NB * LSEQ * HDIM];
__device__ __align__(1024) bf16 g_h1  [(size_t)NB * LSEQ * CHALF];

// smem: 3 stages. A at 0/10240/20480 (128 rows x 80B pitch);
// B at 30720/40960/51200 (non-TRB: 128x80B; TRB: 32 rows x 272B = 8704B)
#define GEMM_SMEM 61440

// ---------------- asm helpers ------------------------------------------------
__device__ __forceinline__ void cp16(uint32_t dst, const void* src) {
    asm volatile("cp.async.cg.shared.global [%0], [%1], 16;"
                 :: "r"(dst), "l"(src) : "memory");
}
#define CP_COMMIT() asm volatile("cp.async.commit_group;" ::: "memory")
#define CP_WAIT1()  asm volatile("cp.async.wait_group 1;" ::: "memory")
#define CP_WAIT0()  asm volatile("cp.async.wait_group 0;" ::: "memory")

__device__ __forceinline__ void ldsm4(uint32_t* r, uint32_t addr) {
    asm volatile("ldmatrix.sync.aligned.m8n8.x4.shared.b16 {%0,%1,%2,%3}, [%4];"
                 : "=r"(r[0]), "=r"(r[1]), "=r"(r[2]), "=r"(r[3]) : "r"(addr));
}
__device__ __forceinline__ void ldsm4t(uint32_t* r, uint32_t addr) {
    asm volatile("ldmatrix.sync.aligned.m8n8.x4.trans.shared.b16 {%0,%1,%2,%3}, [%4];"
                 : "=r"(r[0]), "=r"(r[1]), "=r"(r[2]), "=r"(r[3]) : "r"(addr));
}
__device__ __forceinline__ void mma_bf16(float* c, const uint32_t* a, const uint32_t* b) {
    asm volatile("mma.sync.aligned.m16n8k16.row.col.f32.bf16.bf16.f32 "
                 "{%0,%1,%2,%3},{%4,%5,%6,%7},{%8,%9},{%0,%1,%2,%3};"
                 : "+f"(c[0]), "+f"(c[1]), "+f"(c[2]), "+f"(c[3])
                 : "r"(a[0]), "r"(a[1]), "r"(a[2]), "r"(a[3]), "r"(b[0]), "r"(b[1]));
}

// ---------------- universal bf16 tensor-core GEMM ----------------------------
// TRB=0: C = A[M,K] @ Bt[N,K]^T  (B row stride K, non-trans ldmatrix)
// TRB=1: C = A[M,K] @ B[K,N]     (B row stride N, trans ldmatrix)
// Tile 128x128, BK=32, 3-stage cp.async, ONE __syncthreads per k-iteration.
// EPI: 0 bias->bf16 | 4 bias+leaky->bf16 | 5 bias+tanh+res->fp32
//      7 exp->bf16 (logits)      | 8 scale-by-res[row] ->bf16 (AV normalize)
template <int EPI, bool TRB>
__global__ void __launch_bounds__(256)
gemm5(const bf16* __restrict__ A, const bf16* __restrict__ B,
      const float* __restrict__ bias, const float* __restrict__ res,
      void* __restrict__ Cout, int M, int N, int K, long sA, long sB, long sC)
{
    extern __shared__ __align__(1024) char smem[];
    uint32_t sbase = (uint32_t)__cvta_generic_to_shared(smem);
    const int tid = threadIdx.x, wid = tid >> 5, lane = tid & 31;

    A += (long)blockIdx.z * sA;
    B += (long)blockIdx.z * sB;
    const int m0 = blockIdx.y * 128, n0 = blockIdx.x * 128;

    const int wm = wid >> 2, wn = wid & 3;        // 2x4 warp grid
    const int m_off = wm * 64, n_off = wn * 32;

    float acc[4][4][4];
#pragma unroll
    for (int i = 0; i < 4; i++)
#pragma unroll
        for (int j = 0; j < 4; j++)
#pragma unroll
            for (int u = 0; u < 4; u++) acc[i][j][u] = 0.f;

    const int KT = K >> 5;
    auto ldA = [&](int kt, int buf) {
#pragma unroll
        for (int s = 0; s < 2; s++) {
            int ch = s * 256 + tid;
            int r = ch >> 2, seg = ch & 3;
            cp16(sbase + buf * 10240u + r * 80u + seg * 16u,
                 A + (long)(m0 + r) * K + kt * 32 + seg * 8);
        }
    };
    auto ldB = [&](int kt, int buf) {
        if (!TRB) {
#pragma unroll
            for (int s = 0; s < 2; s++) {
                int ch = s * 256 + tid;
                int r = ch >> 2, seg = ch & 3;
                cp16(sbase + 30720u + buf * 10240u + r * 80u + seg * 16u,
                     B + (long)(n0 + r) * K + kt * 32 + seg * 8);
            }
        } else {
            // [K,N] tile: 32 rows x 256B, pitch 272B
#pragma unroll
            for (int s = 0; s < 2; s++) {
                int ch = s * 256 + tid;
                int r = ch >> 4, seg = ch & 15;
                cp16(sbase + 30720u + buf * 10240u + r * 272u + seg * 16u,
                     B + (long)(kt * 32 + r) * N + n0 + seg * 8);
            }
        }
    };

    ldA(0, 0); ldB(0, 0); CP_COMMIT();
    ldA(1, 1); ldB(1, 1); CP_COMMIT();

    // ldmatrix lane addressing (constant across k-steps)
    const int a_row = m_off + (lane & 15);
    const int a_kof = (lane >> 4) * 8;
    const int b_row = n_off + (lane & 7) + ((lane >> 4) & 1) * 8;
    const int b_kof = ((lane >> 3) & 1) * 8;
    const int t_krow = ((lane >> 3) & 1) * 8 + (lane & 7);
    const int t_ncol = n_off + ((lane >> 4) & 1) * 8;

    int buf = 0;
    for (int kt = 0; kt < KT; kt++) {
        if (kt + 1 < KT) CP_WAIT1(); else CP_WAIT0();
        __syncthreads();                          // single barrier per iter
        if (kt + 2 < KT) {
            int nb = buf + 2; if (nb >= 3) nb -= 3;
            ldA(kt + 2, nb); ldB(kt + 2, nb);
            CP_COMMIT();
        }
        const uint32_t Ab = sbase + buf * 10240u;
        const uint32_t Bb = sbase + 30720u + buf * 10240u;
#pragma unroll
        for (int kk = 0; kk < 32; kk += 16) {
            uint32_t a[4][4], bq[2][4];
#pragma unroll
            for (int mt = 0; mt < 4; mt++)
                ldsm4(a[mt], Ab + ((a_row + mt * 16) * 40 + kk + a_kof) * 2);
            if (!TRB) {
#pragma unroll
                for (int p = 0; p < 2; p++)
                    ldsm4(bq[p], Bb + ((b_row + p * 16) * 40 + kk + b_kof) * 2);
            } else {
#pragma unroll
                for (int p = 0; p < 2; p++)
                    ldsm4t(bq[p], Bb + ((kk + t_krow) * 136 + t_ncol + p * 16) * 2);
            }
#pragma unroll
            for (int mt = 0; mt < 4; mt++)
#pragma unroll
                for (int nt = 0; nt < 4; nt++)
                    mma_bf16(acc[mt][nt], a[mt], &bq[nt >> 1][(nt & 1) * 2]);
        }
        if (++buf == 3) buf = 0;
    }

    // ---- epilogue ----
    const int l4 = lane >> 2, l2 = (lane & 3) * 2;
#pragma unroll
    for (int mt = 0; mt < 4; mt++) {
#pragma unroll
        for (int nt = 0; nt < 4; nt++) {
            int row = m0 + m_off + mt * 16 + l4;
            int col = n0 + n_off + nt * 8 + l2;
            float c0 = acc[mt][nt][0], c1 = acc[mt][nt][1];
            float c2 = acc[mt][nt][2], c3 = acc[mt][nt][3];
            if (EPI == 0 || EPI == 4 || EPI == 5) {
                float b0 = bias[col], b1 = bias[col + 1];
                c0 += b0; c1 += b1; c2 += b0; c3 += b1;
            }
            if (EPI == 4) {
                c0 = fmaxf(c0, 0.2f * c0); c1 = fmaxf(c1, 0.2f * c1);
                c2 = fmaxf(c2, 0.2f * c2); c3 = fmaxf(c3, 0.2f * c3);
            }
            if (EPI == 5) {
                const float2 r0 = *(const float2*)(res + (long)row * N + col);
                const float2 r1 = *(const float2*)(res + (long)(row + 8) * N + col);
                c0 = tanhf(c0) + r0.x; c1 = tanhf(c1) + r0.y;
                c2 = tanhf(c2) + r1.x; c3 = tanhf(c3) + r1.y;
            }
            if (EPI == 7) {                       // unnormalized softmax numerator
                c0 = __expf(c0); c1 = __expf(c1);
                c2 = __expf(c2); c3 = __expf(c3);
            }
            if (EPI == 8) {                       // normalize by 1/rowsum
                const float* inv = res + (long)blockIdx.z * LSEQ;
                float i0 = inv[row], i1 = inv[row + 8];
                c0 *= i0; c1 *= i0; c2 *= i1; c3 *= i1;
            }
            if (EPI == 5) {
                float* Cf = (float*)Cout + (long)blockIdx.z * sC;
                *(float2*)(Cf + (long)row * N + col)       = make_float2(c0, c1);
                *(float2*)(Cf + (long)(row + 8) * N + col) = make_float2(c2, c3);
            } else {
                bf16* Cb = (bf16*)Cout + (long)blockIdx.z * sC;
                *(__nv_bfloat162*)(Cb + (long)row * N + col)       = __floats2bfloat162_rn(c0, c1);
                *(__nv_bfloat162*)(Cb + (long)(row + 8) * N + col) = __floats2bfloat162_rn(c2, c3);
            }
        }
    }
}

// ---------------- row sum of bf16 P' -> 1/sum (deterministic) ----------------
__global__ void __launch_bounds__(256)
rowsum_k(const bf16* __restrict__ P, float* __restrict__ inv)
{
    long base = (long)blockIdx.x * LSEQ;
    const uint4* P8 = (const uint4*)(P + base);     // 8 bf16 per uint4
    int tid = threadIdx.x;
    __shared__ float red[256];

    uint4 v = P8[tid];                               // 256 x 8 = 2048
    const __nv_bfloat162* h = (const __nv_bfloat162*)&v;
    float s = 0.f;
#pragma unroll
    for (int i = 0; i < 4; i++) {
        float2 f = __bfloat1622float2(h[i]);
        s += f.x + f.y;
    }
    red[tid] = s;
    __syncthreads();
    for (int st = 128; st > 0; st >>= 1) {
        if (tid < st) red[tid] += red[tid + st];
        __syncthreads();
    }
    if (tid == 0) inv[blockIdx.x] = 1.f / red[0];
}

// ---------------- conversions ------------------------------------------------
__global__ void __launch_bounds__(256)
f2b_k(const float* __restrict__ in, bf16* __restrict__ out, int n4)
{
    int i = blockIdx.x * 256 + threadIdx.x;
    if (i < n4) {
        float4 v = ((const float4*)in)[i];
        ((__nv_bfloat162*)out)[2 * i]     = __floats2bfloat162_rn(v.x, v.y);
        ((__nv_bfloat162*)out)[2 * i + 1] = __floats2bfloat162_rn(v.z, v.w);
    }
}

// all 5 weights fp32 -> bf16 (same [K,N] layout, no transpose) in one launch
__global__ void __launch_bounds__(256)
w2b_k(const float* __restrict__ thw, const float* __restrict__ phw,
      const float* __restrict__ psw, const float* __restrict__ r1w,
      const float* __restrict__ r2w,
      bf16* __restrict__ oth, bf16* __restrict__ oph, bf16* __restrict__ ops,
      bf16* __restrict__ or1, bf16* __restrict__ or2)
{
    int i = blockIdx.x * 256 + threadIdx.x;      // float4 index, 262144 total
    const float* src;
    bf16* dst;
    int off;
    if (i < 196608) {
        int w = i / 65536; off = i - w * 65536;
        src = (w == 0) ? thw : (w == 1) ? phw : psw;
        dst = (w == 0) ? oth : (w == 1) ? oph : ops;
    } else if (i < 229376) {
        off = i - 196608; src = r1w; dst = or1;
    } else {
        off = i - 229376; src = r2w; dst = or2;
    }
    float4 v = ((const float4*)src)[off];
    ((__nv_bfloat162*)dst)[2 * off]     = __floats2bfloat162_rn(v.x, v.y);
    ((__nv_bfloat162*)dst)[2 * off + 1] = __floats2bfloat162_rn(v.z, v.w);
}

// ---------------- launch ----------------------------------------------------
extern "C" void kernel_launch(void* const* d_in, const int* in_sizes, int n_in,
                              void* d_out, int out_size)
{
    const float* x   = (const float*)d_in[0];
    const float* thw = (const float*)d_in[1];
    const float* thb = (const float*)d_in[2];
    const float* phw = (const float*)d_in[3];
    const float* phb = (const float*)d_in[4];
    const float* psw = (const float*)d_in[5];
    const float* psb = (const float*)d_in[6];
    const float* r1w = (const float*)d_in[7];
    const float* r1b = (const float*)d_in[8];
    const float* r2w = (const float*)d_in[9];
    const float* r2b = (const float*)d_in[10];
    float* out = (float*)d_out;

    bf16 *p_xb, *p_wth, *p_wph, *p_wps, *p_wr1, *p_wr2;
    bf16 *p_xt, *p_xph, *p_xpsi, *p_P, *p_xadd, *p_h1;
    float *p_rs;
    cudaGetSymbolAddress((void**)&p_xb,   g_xb);
    cudaGetSymbolAddress((void**)&p_wth,  g_wth);
    cudaGetSymbolAddress((void**)&p_wph,  g_wph);
    cudaGetSymbolAddress((void**)&p_wps,  g_wps);
    cudaGetSymbolAddress((void**)&p_wr1,  g_wr1);
    cudaGetSymbolAddress((void**)&p_wr2,  g_wr2);
    cudaGetSymbolAddress((void**)&p_xt,   g_xt);
    cudaGetSymbolAddress((void**)&p_xph,  g_xph);
    cudaGetSymbolAddress((void**)&p_xpsi, g_xpsi);
    cudaGetSymbolAddress((void**)&p_P,    g_P);
    cudaGetSymbolAddress((void**)&p_rs,   g_rs);
    cudaGetSymbolAddress((void**)&p_xadd, g_xadd);
    cudaGetSymbolAddress((void**)&p_h1,   g_h1);

    cudaFuncSetAttribute((const void*)gemm5<0, true>,  cudaFuncAttributeMaxDynamicSharedMemorySize, GEMM_SMEM);
    cudaFuncSetAttribute((const void*)gemm5<7, false>, cudaFuncAttributeMaxDynamicSharedMemorySize, GEMM_SMEM);
    cudaFuncSetAttribute((const void*)gemm5<8, true>,  cudaFuncAttributeMaxDynamicSharedMemorySize, GEMM_SMEM);
    cudaFuncSetAttribute((const void*)gemm5<4, true>,  cudaFuncAttributeMaxDynamicSharedMemorySize, GEMM_SMEM);
    cudaFuncSetAttribute((const void*)gemm5<5, true>,  cudaFuncAttributeMaxDynamicSharedMemorySize, GEMM_SMEM);

    const int M = NB * LSEQ;                 // 16384
    const long sLH = (long)LSEQ * HDIM;
    const long sLL = (long)LSEQ * LSEQ;
    dim3 gproj(HDIM / 128, M / 128, 1);

    // launches ordered so #6 (ncu -s 5 -c 1) is the logits GEMM
    f2b_k<<<(M * CDIM / 4 + 255) / 256, 256>>>(x, p_xb, M * CDIM / 4);          // 1
    w2b_k<<<1024, 256>>>(thw, phw, psw, r1w, r2w,                               // 2
                         p_wth, p_wph, p_wps, p_wr1, p_wr2);
    gemm5<0, true><<<gproj, 256, GEMM_SMEM>>>(p_xb, p_wth, thb, nullptr, p_xt,  // 3
                                              M, HDIM, CDIM, 0, 0, 0);
    gemm5<0, true><<<gproj, 256, GEMM_SMEM>>>(p_xb, p_wph, phb, nullptr, p_xph, // 4
                                              M, HDIM, CDIM, 0, 0, 0);
    gemm5<0, true><<<gproj, 256, GEMM_SMEM>>>(p_xb, p_wps, psb, nullptr, p_xpsi,// 5
                                              M, HDIM, CDIM, 0, 0, 0);
    // 6: logits -> P' = exp(s) in bf16 (no fp32 S, no separate softmax)
    gemm5<7, false><<<dim3(LSEQ / 128, LSEQ / 128, NB), 256, GEMM_SMEM>>>(
        p_xph, p_xt, nullptr, nullptr, p_P, LSEQ, LSEQ, HDIM, sLH, sLH, sLL);
    // 7: deterministic row sums -> 1/sum
    rowsum_k<<<NB * LSEQ, 256>>>(p_P, p_rs);
    // 8: x_add = (P' @ x_psi) * inv[row]
    gemm5<8, true><<<dim3(HDIM / 128, LSEQ / 128, NB), 256, GEMM_SMEM>>>(
        p_P, p_xpsi, nullptr, p_rs, p_xadd, LSEQ, HDIM, LSEQ, sLL, sLH, sLH);
    // 9: h1 = leaky_relu(x_add @ r1w + r1b)
    gemm5<4, true><<<dim3(CHALF / 128, M / 128, 1), 256, GEMM_SMEM>>>(
        p_xadd, p_wr1, r1b, nullptr, p_h1, M, CHALF, HDIM, 0, 0, 0);
    // 10: out = x + tanh(h1 @ r2w + r2b)
    gemm5<5, true><<<dim3(CDIM / 128, M / 128, 1), 256, GEMM_SMEM>>>(
        p_h1, p_wr2, r2b, x, out, M, CDIM, CHALF, 0, 0, 0);
}